// round 2
// baseline (speedup 1.0000x reference)
#include <cuda_runtime.h>

#define Bsz 4
#define Ssz 512
#define Dsz 768
#define Hn  12
#define DHn 64
#define SDn 30

// ---- scratch (static device globals; no runtime allocation) ----
__device__ float g_q  [Bsz*Hn*Ssz*DHn];          // (B,H,S,DH) scaled q
__device__ float g_k  [Bsz*Hn*Ssz*DHn];
__device__ float g_v  [Bsz*Hn*Ssz*DHn];
__device__ float g_ctx[Bsz*Ssz*Dsz];             // (B,S,H*DH)
__device__ float g_qs [Bsz*Hn*Ssz*SDn];          // q @ Wsk^T
__device__ float g_A  [Bsz*Hn*Ssz*SDn];          // attn . structure
__device__ float g_sc [(size_t)Bsz*Hn*Ssz*Ssz];  // scores / attn (in place)
__device__ int   g_maskmode;                     // 1 = byte mask, 0 = int32 mask

// Detect mask storage: scan first n_words int32 words (in-bounds for both
// layouts). Random 0/1 bytes packed into int32 produce values > 1 with
// certainty; true int32 bool is always 0/1.
__global__ void detect_mask(const unsigned int* __restrict__ m, int n_words)
{
    __shared__ int found;
    if (threadIdx.x == 0) found = 0;
    __syncthreads();
    for (int i = threadIdx.x; i < n_words; i += blockDim.x) {
        if (m[i] > 1u) { found = 1; break; }
    }
    __syncthreads();
    if (threadIdx.x == 0) g_maskmode = found;
}

// ---------------------------------------------------------------------------
// Generic fp32 tiled GEMM: 64x64 tile, BK=16, 256 threads, 4x4 micro-tile.
// ---------------------------------------------------------------------------
__global__ void gemm64(const float* __restrict__ A, const float* __restrict__ Bm,
                       const float* __restrict__ bias, float* __restrict__ C,
                       int M, int N, int K,
                       long aBatch, long bBatch,
                       long cB, long cH, int ldc,
                       int transB, float scale, int headLayout)
{
    __shared__ float As[16][65];
    __shared__ float Bs[16][65];
    int tid = threadIdx.x;
    int tx = tid & 15, ty = tid >> 4;
    int z = blockIdx.z;
    const float* Ab = A + (long)z * aBatch + (long)blockIdx.y * 64 * K;
    const float* Bb = Bm + (long)z * bBatch;
    float acc[4][4] = {};

    for (int k0 = 0; k0 < K; k0 += 16) {
        #pragma unroll
        for (int i = 0; i < 4; i++) {
            int idx = tid + 256 * i;
            int m = idx >> 4, kk = idx & 15;
            As[kk][m] = Ab[(long)m * K + k0 + kk];
        }
        if (!transB) {
            #pragma unroll
            for (int i = 0; i < 4; i++) {
                int idx = tid + 256 * i;
                int kk = idx >> 6, n = idx & 63;
                Bs[kk][n] = Bb[(long)(k0 + kk) * N + blockIdx.x * 64 + n];
            }
        } else {
            #pragma unroll
            for (int i = 0; i < 4; i++) {
                int idx = tid + 256 * i;
                int n = idx >> 4, kk = idx & 15;
                Bs[kk][n] = Bb[(long)(blockIdx.x * 64 + n) * K + k0 + kk];
            }
        }
        __syncthreads();
        #pragma unroll
        for (int kk = 0; kk < 16; kk++) {
            float a[4], bb[4];
            #pragma unroll
            for (int i = 0; i < 4; i++) a[i] = As[kk][ty * 4 + i];
            #pragma unroll
            for (int j = 0; j < 4; j++) bb[j] = Bs[kk][tx * 4 + j];
            #pragma unroll
            for (int i = 0; i < 4; i++)
                #pragma unroll
                for (int j = 0; j < 4; j++) acc[i][j] += a[i] * bb[j];
        }
        __syncthreads();
    }

    #pragma unroll
    for (int i = 0; i < 4; i++) {
        int m = blockIdx.y * 64 + ty * 4 + i;
        #pragma unroll
        for (int j = 0; j < 4; j++) {
            int n = blockIdx.x * 64 + tx * 4 + j;
            float v = acc[i][j];
            if (bias) v += bias[n];
            v *= scale;
            long off;
            if (headLayout) {
                int b = m >> 9, s = m & 511;
                int h = n >> 6, d = n & 63;
                off = (((long)b * Hn + h) * Ssz + s) * DHn + d;
            } else {
                off = (long)(z / Hn) * cB + (long)(z % Hn) * cH + (long)m * ldc + n;
            }
            C[off] = v;
        }
    }
}

// qs[b,h,q,s] = sum_d q[b,h,q,d] * Wsk[s,d]
__global__ void qs_kernel(const float* __restrict__ q, const float* __restrict__ Wsk,
                          float* __restrict__ qs)
{
    int tid = threadIdx.x;
    int rl = tid / 30, s = tid % 30;
    long r = (long)blockIdx.x * 8 + rl;
    const float* qr = q + r * 64;
    const float* w = Wsk + s * 64;
    float acc = 0.f;
    #pragma unroll
    for (int d = 0; d < 64; d++) acc += qr[d] * w[d];
    qs[r * 30 + s] = acc;
}

// scores[b,h,q,k] += sum_s qs[b,h,q,s]*structure[b,q,k,s]; apply mask -> -1e18
__global__ void add_struct(const float* __restrict__ structure, const float* __restrict__ qs,
                           const void* __restrict__ mask, float* __restrict__ sc)
{
    __shared__ float st[64][31];
    __shared__ float qss[12][30];
    __shared__ unsigned char mk[64];
    int tid = threadIdx.x;
    int k0 = blockIdx.x * 64, qrow = blockIdx.y, b = blockIdx.z;
    const float* sb = structure + (((long)(b * Ssz + qrow)) * Ssz + k0) * SDn;
    for (int idx = tid; idx < 64 * 30; idx += 256) st[idx / 30][idx % 30] = sb[idx];
    for (int idx = tid; idx < 360; idx += 256)
        qss[idx / 30][idx % 30] =
            qs[(((long)(b * Hn + idx / 30)) * Ssz + qrow) * SDn + idx % 30];
    if (tid < 64) {
        long moff = ((long)(b * Ssz + qrow)) * Ssz + k0 + tid;
        mk[tid] = g_maskmode ? ((const unsigned char*)mask)[moff]
                             : (unsigned char)(((const int*)mask)[moff] != 0);
    }
    __syncthreads();
    for (int o = tid; o < 768; o += 256) {
        int h = o >> 6, kk = o & 63;
        long idx = (((long)(b * Hn + h)) * Ssz + qrow) * Ssz + k0 + kk;
        if (mk[kk]) {
            sc[idx] = -1e18f;
        } else {
            float acc = sc[idx];
            #pragma unroll
            for (int s = 0; s < 30; s++) acc += qss[h][s] * st[kk][s];
            sc[idx] = acc;
        }
    }
}

// row softmax over k (512), in place; head 0 also written to top_attn output.
__global__ void softmax_kernel(float* __restrict__ sc, float* __restrict__ top)
{
    int qrow = blockIdx.x, h = blockIdx.y, b = blockIdx.z;
    float* row = sc + (((long)(b * Hn + h)) * Ssz + qrow) * Ssz;
    int tid = threadIdx.x;
    float v[4];
    #pragma unroll
    for (int i = 0; i < 4; i++) v[i] = row[tid + 128 * i];
    float m = fmaxf(fmaxf(v[0], v[1]), fmaxf(v[2], v[3]));
    #pragma unroll
    for (int o = 16; o > 0; o >>= 1) m = fmaxf(m, __shfl_xor_sync(0xffffffffu, m, o));
    __shared__ float redm[4];
    __shared__ float reds[4];
    if ((tid & 31) == 0) redm[tid >> 5] = m;
    __syncthreads();
    m = fmaxf(fmaxf(redm[0], redm[1]), fmaxf(redm[2], redm[3]));
    float e[4];
    float s = 0.f;
    #pragma unroll
    for (int i = 0; i < 4; i++) { e[i] = __expf(v[i] - m); s += e[i]; }
    #pragma unroll
    for (int o = 16; o > 0; o >>= 1) s += __shfl_xor_sync(0xffffffffu, s, o);
    if ((tid & 31) == 0) reds[tid >> 5] = s;
    __syncthreads();
    s = reds[0] + reds[1] + reds[2] + reds[3];
    float inv = 1.0f / s;
    #pragma unroll
    for (int i = 0; i < 4; i++) {
        float w = e[i] * inv;
        row[tid + 128 * i] = w;
        if (h == 0) top[((long)(b * Ssz + qrow)) * Ssz + tid + 128 * i] = w;
    }
}

// A[b,h,q,s] = sum_k attn[b,h,q,k]*structure[b,q,k,s]
__global__ void acc_A(const float* __restrict__ attn, const float* __restrict__ structure,
                      float* __restrict__ Aout)
{
    __shared__ float st[64][31];
    __shared__ float at[12][64];
    int tid = threadIdx.x;
    int qrow = blockIdx.x, b = blockIdx.y;
    float acc = 0.f;
    int h = tid / 30, s = tid % 30;
    for (int kt = 0; kt < 8; kt++) {
        const float* sb = structure + (((long)(b * Ssz + qrow)) * Ssz + kt * 64) * SDn;
        for (int idx = tid; idx < 1920; idx += 384) st[idx / 30][idx % 30] = sb[idx];
        for (int idx = tid; idx < 768; idx += 384)
            at[idx >> 6][idx & 63] =
                attn[(((long)(b * Hn + (idx >> 6))) * Ssz + qrow) * Ssz + kt * 64 + (idx & 63)];
        __syncthreads();
        if (tid < 360) {
            #pragma unroll
            for (int k = 0; k < 64; k++) acc += at[h][k] * st[k][s];
        }
        __syncthreads();
    }
    if (tid < 360)
        Aout[(((long)(b * Hn + h)) * Ssz + qrow) * SDn + s] = acc;
}

// ctx[b,s,h*64+d] += sum_s A[b,h,q,s]*Wsv[s,d] + bsv[d]
__global__ void add_sv(const float* __restrict__ A, const float* __restrict__ Wsv,
                       const float* __restrict__ bsv, float* __restrict__ ctx)
{
    int tid = threadIdx.x;
    long r = (long)blockIdx.x * 4 + (tid >> 6);
    int d = tid & 63;
    const float* ar = A + r * 30;
    float acc = bsv[d];
    #pragma unroll
    for (int s = 0; s < 30; s++) acc += ar[s] * Wsv[s * 64 + d];
    int b = (int)(r / (Hn * Ssz));
    int h = (int)((r / Ssz) % Hn);
    int qrow = (int)(r % Ssz);
    ctx[(((long)(b * Ssz + qrow)) * Dsz) + h * 64 + d] += acc;
}

extern "C" void kernel_launch(void* const* d_in, const int* in_sizes, int n_in,
                              void* d_out, int out_size)
{
    const float* key       = (const float*)d_in[0];
    const float* value     = (const float*)d_in[1];
    const float* query     = (const float*)d_in[2];
    const float* structure = (const float*)d_in[3];
    const void*  mask      = d_in[4];
    const float* Wq  = (const float*)d_in[5];
    const float* bq  = (const float*)d_in[6];
    const float* Wk  = (const float*)d_in[7];
    const float* bk  = (const float*)d_in[8];
    const float* Wv  = (const float*)d_in[9];
    const float* bv  = (const float*)d_in[10];
    const float* Wsk = (const float*)d_in[11];
    // d_in[12] = bsk : softmax-invariant (constant over k), dropped.
    const float* Wsv = (const float*)d_in[13];
    const float* bsv = (const float*)d_in[14];
    const float* Wo  = (const float*)d_in[15];
    const float* bo  = (const float*)d_in[16];
    float* out = (float*)d_out;
    float* out_top = out + (long)Bsz * Ssz * Dsz;

    float *q, *k, *v, *ctx, *qs, *Aacc, *sc;
    cudaGetSymbolAddress((void**)&q,    g_q);
    cudaGetSymbolAddress((void**)&k,    g_k);
    cudaGetSymbolAddress((void**)&v,    g_v);
    cudaGetSymbolAddress((void**)&ctx,  g_ctx);
    cudaGetSymbolAddress((void**)&qs,   g_qs);
    cudaGetSymbolAddress((void**)&Aacc, g_A);
    cudaGetSymbolAddress((void**)&sc,   g_sc);

    const float qscale = 0.125f; // 1/sqrt(64)
    const int mask_elems = Bsz * Ssz * Ssz;

    // resolve mask representation (int32 vs byte), deterministic
    detect_mask<<<1, 256>>>((const unsigned int*)mask, mask_elems / 4);

    // projections -> (B,H,S,DH)
    gemm64<<<dim3(12, 32, 1), 256>>>(query, Wq, bq, q, 2048, 768, 768,
                                     0, 0, 0, 0, 768, 0, qscale, 1);
    gemm64<<<dim3(12, 32, 1), 256>>>(key, Wk, bk, k, 2048, 768, 768,
                                     0, 0, 0, 0, 768, 0, 1.0f, 1);
    gemm64<<<dim3(12, 32, 1), 256>>>(value, Wv, bv, v, 2048, 768, 768,
                                     0, 0, 0, 0, 768, 0, 1.0f, 1);
    // qs = q @ Wsk^T
    qs_kernel<<<3072, 240>>>(q, Wsk, qs);
    // scores = q @ k^T  (batched over b*h = 48)
    gemm64<<<dim3(8, 8, 48), 256>>>(q, k, nullptr, sc, 512, 512, 64,
                                    (long)Ssz * DHn, (long)Ssz * DHn,
                                    (long)Hn * Ssz * Ssz, (long)Ssz * Ssz, Ssz,
                                    1, 1.0f, 0);
    // scores += qs . structure ; mask
    add_struct<<<dim3(8, 512, 4), 256>>>(structure, qs, mask, sc);
    // softmax (+ top_attn for h==0)
    softmax_kernel<<<dim3(512, 12, 4), 128>>>(sc, out_top);
    // ctx = attn @ v  -> (B,S,H*DH)
    gemm64<<<dim3(1, 8, 48), 256>>>(sc, v, nullptr, ctx, 512, 64, 512,
                                    (long)Ssz * Ssz, (long)Ssz * DHn,
                                    (long)Ssz * Dsz, 64, Dsz,
                                    0, 1.0f, 0);
    // A = attn . structure
    acc_A<<<dim3(512, 4), 384>>>(sc, structure, Aacc);
    // ctx += A @ Wsv + bsv
    add_sv<<<6144, 256>>>(Aacc, Wsv, bsv, ctx);
    // out = ctx @ Wo + bo
    gemm64<<<dim3(12, 32, 1), 256>>>(ctx, Wo, bo, out, 2048, 768, 768,
                                     0, 0, 0, 0, 768, 0, 1.0f, 0);
}

// round 5
// speedup vs baseline: 1.1191x; 1.1191x over previous
#include <cuda_runtime.h>

#define Bsz 4
#define Ssz 512
#define Dsz 768
#define Hn  12
#define DHn 64
#define SDn 30

// ---- scratch (static device globals; no runtime allocation) ----
__device__ float g_q  [Bsz*Hn*Ssz*DHn];          // (B,H,S,DH) scaled q
__device__ float g_k  [Bsz*Hn*Ssz*DHn];
__device__ float g_v  [Bsz*Hn*Ssz*DHn];
__device__ float g_ctx[Bsz*Ssz*Dsz];             // (B,S,H*DH)
__device__ float g_qs [Bsz*Hn*Ssz*SDn];          // q @ Wsk^T
__device__ float g_A  [Bsz*Hn*Ssz*SDn];          // attn . structure
__device__ float g_sc [(size_t)Bsz*Hn*Ssz*Ssz];  // scores / attn (in place)
__device__ int   g_maskmode;                     // 1 = byte mask, 0 = int32 mask

__global__ void detect_mask(const unsigned int* __restrict__ m, int n_words)
{
    __shared__ int found;
    if (threadIdx.x == 0) found = 0;
    __syncthreads();
    for (int i = threadIdx.x; i < n_words; i += blockDim.x) {
        if (m[i] > 1u) { found = 1; break; }
    }
    __syncthreads();
    if (threadIdx.x == 0) g_maskmode = found;
}

// ---------------------------------------------------------------------------
// fp32 GEMM: 128x64 tile, BK=16, 256 threads, 8x4 micro-tile, double-buffered
// smem, float4 global+shared loads. C = scale*(A@B (+bias)).
// All dims are exact multiples of tile sizes for this problem.
// ---------------------------------------------------------------------------
#define AS_STRIDE 132
#define BS_STRIDE 68

__global__ void __launch_bounds__(256, 2)
gemm_big(const float* __restrict__ A, const float* __restrict__ Bm,
         const float* __restrict__ bias, float* __restrict__ C,
         int M, int N, int K,
         long aBatch, long bBatch,
         long cB, long cH, int ldc,
         int transB, float scale, int headLayout)
{
    __shared__ float As[2][16 * AS_STRIDE];
    __shared__ float Bs[2][16 * BS_STRIDE];
    int tid = threadIdx.x;
    int tx = tid & 15, ty = tid >> 4;
    int z = blockIdx.z;
    const float* Ab = A + (long)z * aBatch + (long)blockIdx.y * 128 * K;
    const float* Bb = Bm + (long)z * bBatch;

    // load-phase indices
    int am = tid >> 2, akv = (tid & 3) * 4;        // A: 64 rows x 4 f4 cols, x2 phases
    int bkk = tid >> 4, bnv = (tid & 15) * 4;      // B non-trans
    int bn  = tid >> 2, bkv = (tid & 3) * 4;       // B trans

    float acc[8][4] = {};
    int nt = K / 16;

    // prologue: tile 0 -> smem[0]
    {
        const float* Ap = Ab + (long)am * K + akv;
        float4 ra0 = *(const float4*)Ap;
        float4 ra1 = *(const float4*)(Ap + (long)64 * K);
        #pragma unroll
        for (int j = 0; j < 4; j++) {
            As[0][(akv + j) * AS_STRIDE + am]      = (&ra0.x)[j];
            As[0][(akv + j) * AS_STRIDE + am + 64] = (&ra1.x)[j];
        }
        if (!transB) {
            float4 rb = *(const float4*)(Bb + (long)bkk * N + blockIdx.x * 64 + bnv);
            *(float4*)&Bs[0][bkk * BS_STRIDE + bnv] = rb;
        } else {
            float4 rb = *(const float4*)(Bb + (long)(blockIdx.x * 64 + bn) * K + bkv);
            #pragma unroll
            for (int j = 0; j < 4; j++) Bs[0][(bkv + j) * BS_STRIDE + bn] = (&rb.x)[j];
        }
    }
    __syncthreads();

    int cur = 0;
    for (int kt = 0; kt < nt; kt++) {
        float4 ra0, ra1, rb;
        bool pre = (kt + 1 < nt);
        if (pre) {
            int k0 = (kt + 1) * 16;
            const float* Ap = Ab + (long)am * K + k0 + akv;
            ra0 = *(const float4*)Ap;
            ra1 = *(const float4*)(Ap + (long)64 * K);
            if (!transB)
                rb = *(const float4*)(Bb + (long)(k0 + bkk) * N + blockIdx.x * 64 + bnv);
            else
                rb = *(const float4*)(Bb + (long)(blockIdx.x * 64 + bn) * K + k0 + bkv);
        }
        const float* as = As[cur];
        const float* bs = Bs[cur];
        #pragma unroll
        for (int kk = 0; kk < 16; kk++) {
            float4 a0 = *(const float4*)&as[kk * AS_STRIDE + ty * 8];
            float4 a1 = *(const float4*)&as[kk * AS_STRIDE + ty * 8 + 4];
            float4 b  = *(const float4*)&bs[kk * BS_STRIDE + tx * 4];
            float av[8] = {a0.x, a0.y, a0.z, a0.w, a1.x, a1.y, a1.z, a1.w};
            float bv[4] = {b.x, b.y, b.z, b.w};
            #pragma unroll
            for (int i = 0; i < 8; i++)
                #pragma unroll
                for (int j = 0; j < 4; j++) acc[i][j] += av[i] * bv[j];
        }
        if (pre) {
            int nxt = cur ^ 1;
            #pragma unroll
            for (int j = 0; j < 4; j++) {
                As[nxt][(akv + j) * AS_STRIDE + am]      = (&ra0.x)[j];
                As[nxt][(akv + j) * AS_STRIDE + am + 64] = (&ra1.x)[j];
            }
            if (!transB) {
                *(float4*)&Bs[nxt][bkk * BS_STRIDE + bnv] = rb;
            } else {
                #pragma unroll
                for (int j = 0; j < 4; j++) Bs[nxt][(bkv + j) * BS_STRIDE + bn] = (&rb.x)[j];
            }
            __syncthreads();
            cur = nxt;
        }
    }

    #pragma unroll
    for (int i = 0; i < 8; i++) {
        int m = blockIdx.y * 128 + ty * 8 + i;
        #pragma unroll
        for (int j = 0; j < 4; j++) {
            int n = blockIdx.x * 64 + tx * 4 + j;
            float v = acc[i][j];
            if (bias) v += bias[n];
            v *= scale;
            long off;
            if (headLayout) {
                int b = m >> 9, s = m & 511;
                int h = n >> 6, d = n & 63;
                off = (((long)b * Hn + h) * Ssz + s) * DHn + d;
            } else {
                off = (long)(z / Hn) * cB + (long)(z % Hn) * cH + (long)m * ldc + n;
            }
            C[off] = v;
        }
    }
}

// qs[b,h,q,s] = sum_d q[b,h,q,d] * Wsk[s,d]
__global__ void qs_kernel(const float* __restrict__ q, const float* __restrict__ Wsk,
                          float* __restrict__ qs)
{
    int tid = threadIdx.x;
    int rl = tid / 30, s = tid % 30;
    long r = (long)blockIdx.x * 8 + rl;
    const float* qr = q + r * 64;
    const float* w = Wsk + s * 64;
    float acc = 0.f;
    #pragma unroll
    for (int d = 0; d < 64; d++) acc += qr[d] * w[d];
    qs[r * 30 + s] = acc;
}

// scores[b,h,q,k] += sum_s qs[b,h,q,s]*structure[b,q,k,s]; apply mask -> -1e18
__global__ void add_struct(const float* __restrict__ structure, const float* __restrict__ qs,
                           const void* __restrict__ mask, float* __restrict__ sc)
{
    __shared__ float st[64][31];
    __shared__ float qss[12][30];
    __shared__ unsigned char mk[64];
    int tid = threadIdx.x;
    int k0 = blockIdx.x * 64, qrow = blockIdx.y, b = blockIdx.z;
    const float* sb = structure + (((long)(b * Ssz + qrow)) * Ssz + k0) * SDn;
    for (int idx = tid; idx < 64 * 30; idx += 256) st[idx / 30][idx % 30] = sb[idx];
    for (int idx = tid; idx < 360; idx += 256)
        qss[idx / 30][idx % 30] =
            qs[(((long)(b * Hn + idx / 30)) * Ssz + qrow) * SDn + idx % 30];
    if (tid < 64) {
        long moff = ((long)(b * Ssz + qrow)) * Ssz + k0 + tid;
        mk[tid] = g_maskmode ? ((const unsigned char*)mask)[moff]
                             : (unsigned char)(((const int*)mask)[moff] != 0);
    }
    __syncthreads();
    for (int o = tid; o < 768; o += 256) {
        int h = o >> 6, kk = o & 63;
        long idx = (((long)(b * Hn + h)) * Ssz + qrow) * Ssz + k0 + kk;
        if (mk[kk]) {
            sc[idx] = -1e18f;
        } else {
            float acc = sc[idx];
            #pragma unroll
            for (int s = 0; s < 30; s++) acc += qss[h][s] * st[kk][s];
            sc[idx] = acc;
        }
    }
}

// row softmax over k (512), in place; head 0 also written to top_attn output.
__global__ void softmax_kernel(float* __restrict__ sc, float* __restrict__ top)
{
    int qrow = blockIdx.x, h = blockIdx.y, b = blockIdx.z;
    float* row = sc + (((long)(b * Hn + h)) * Ssz + qrow) * Ssz;
    int tid = threadIdx.x;
    float v[4];
    #pragma unroll
    for (int i = 0; i < 4; i++) v[i] = row[tid + 128 * i];
    float m = fmaxf(fmaxf(v[0], v[1]), fmaxf(v[2], v[3]));
    #pragma unroll
    for (int o = 16; o > 0; o >>= 1) m = fmaxf(m, __shfl_xor_sync(0xffffffffu, m, o));
    __shared__ float redm[4];
    __shared__ float reds[4];
    if ((tid & 31) == 0) redm[tid >> 5] = m;
    __syncthreads();
    m = fmaxf(fmaxf(redm[0], redm[1]), fmaxf(redm[2], redm[3]));
    float e[4];
    float s = 0.f;
    #pragma unroll
    for (int i = 0; i < 4; i++) { e[i] = __expf(v[i] - m); s += e[i]; }
    #pragma unroll
    for (int o = 16; o > 0; o >>= 1) s += __shfl_xor_sync(0xffffffffu, s, o);
    if ((tid & 31) == 0) reds[tid >> 5] = s;
    __syncthreads();
    s = reds[0] + reds[1] + reds[2] + reds[3];
    float inv = 1.0f / s;
    #pragma unroll
    for (int i = 0; i < 4; i++) {
        float w = e[i] * inv;
        row[tid + 128 * i] = w;
        if (h == 0) top[((long)(b * Ssz + qrow)) * Ssz + tid + 128 * i] = w;
    }
}

// A[b,h,q,s] = sum_k attn[b,h,q,k]*structure[b,q,k,s]
__global__ void acc_A(const float* __restrict__ attn, const float* __restrict__ structure,
                      float* __restrict__ Aout)
{
    __shared__ float st[64][31];
    __shared__ float at[12][64];
    int tid = threadIdx.x;
    int qrow = blockIdx.x, b = blockIdx.y;
    float acc = 0.f;
    int h = tid / 30, s = tid % 30;
    for (int kt = 0; kt < 8; kt++) {
        const float* sb = structure + (((long)(b * Ssz + qrow)) * Ssz + kt * 64) * SDn;
        for (int idx = tid; idx < 1920; idx += 384) st[idx / 30][idx % 30] = sb[idx];
        for (int idx = tid; idx < 768; idx += 384)
            at[idx >> 6][idx & 63] =
                attn[(((long)(b * Hn + (idx >> 6))) * Ssz + qrow) * Ssz + kt * 64 + (idx & 63)];
        __syncthreads();
        if (tid < 360) {
            #pragma unroll
            for (int k = 0; k < 64; k++) acc += at[h][k] * st[k][s];
        }
        __syncthreads();
    }
    if (tid < 360)
        Aout[(((long)(b * Hn + h)) * Ssz + qrow) * SDn + s] = acc;
}

// ctx[b,s,h*64+d] += sum_s A[b,h,q,s]*Wsv[s,d] + bsv[d]
__global__ void add_sv(const float* __restrict__ A, const float* __restrict__ Wsv,
                       const float* __restrict__ bsv, float* __restrict__ ctx)
{
    int tid = threadIdx.x;
    long r = (long)blockIdx.x * 4 + (tid >> 6);
    int d = tid & 63;
    const float* ar = A + r * 30;
    float acc = bsv[d];
    #pragma unroll
    for (int s = 0; s < 30; s++) acc += ar[s] * Wsv[s * 64 + d];
    int b = (int)(r / (Hn * Ssz));
    int h = (int)((r / Ssz) % Hn);
    int qrow = (int)(r % Ssz);
    ctx[(((long)(b * Ssz + qrow)) * Dsz) + h * 64 + d] += acc;
}

extern "C" void kernel_launch(void* const* d_in, const int* in_sizes, int n_in,
                              void* d_out, int out_size)
{
    const float* key       = (const float*)d_in[0];
    const float* value     = (const float*)d_in[1];
    const float* query     = (const float*)d_in[2];
    const float* structure = (const float*)d_in[3];
    const void*  mask      = d_in[4];
    const float* Wq  = (const float*)d_in[5];
    const float* bq  = (const float*)d_in[6];
    const float* Wk  = (const float*)d_in[7];
    const float* bk  = (const float*)d_in[8];
    const float* Wv  = (const float*)d_in[9];
    const float* bv  = (const float*)d_in[10];
    const float* Wsk = (const float*)d_in[11];
    // d_in[12] = bsk : softmax-invariant (constant over k), dropped.
    const float* Wsv = (const float*)d_in[13];
    const float* bsv = (const float*)d_in[14];
    const float* Wo  = (const float*)d_in[15];
    const float* bo  = (const float*)d_in[16];
    float* out = (float*)d_out;
    float* out_top = out + (long)Bsz * Ssz * Dsz;

    float *q, *k, *v, *ctx, *qs, *Aacc, *sc;
    cudaGetSymbolAddress((void**)&q,    g_q);
    cudaGetSymbolAddress((void**)&k,    g_k);
    cudaGetSymbolAddress((void**)&v,    g_v);
    cudaGetSymbolAddress((void**)&ctx,  g_ctx);
    cudaGetSymbolAddress((void**)&qs,   g_qs);
    cudaGetSymbolAddress((void**)&Aacc, g_A);
    cudaGetSymbolAddress((void**)&sc,   g_sc);

    const float qscale = 0.125f; // 1/sqrt(64)
    const int mask_elems = Bsz * Ssz * Ssz;

    detect_mask<<<1, 256>>>((const unsigned int*)mask, mask_elems / 4);

    // projections -> (B,H,S,DH)   M=2048,N=768,K=768; tiles 128x64
    gemm_big<<<dim3(12, 16, 1), 256>>>(query, Wq, bq, q, 2048, 768, 768,
                                       0, 0, 0, 0, 768, 0, qscale, 1);
    gemm_big<<<dim3(12, 16, 1), 256>>>(key, Wk, bk, k, 2048, 768, 768,
                                       0, 0, 0, 0, 768, 0, 1.0f, 1);
    gemm_big<<<dim3(12, 16, 1), 256>>>(value, Wv, bv, v, 2048, 768, 768,
                                       0, 0, 0, 0, 768, 0, 1.0f, 1);
    // qs = q @ Wsk^T
    qs_kernel<<<3072, 240>>>(q, Wsk, qs);
    // scores = q @ k^T  (batched over b*h = 48)
    gemm_big<<<dim3(8, 4, 48), 256>>>(q, k, nullptr, sc, 512, 512, 64,
                                      (long)Ssz * DHn, (long)Ssz * DHn,
                                      (long)Hn * Ssz * Ssz, (long)Ssz * Ssz, Ssz,
                                      1, 1.0f, 0);
    // scores += qs . structure ; mask
    add_struct<<<dim3(8, 512, 4), 256>>>(structure, qs, mask, sc);
    // softmax (+ top_attn for h==0)
    softmax_kernel<<<dim3(512, 12, 4), 128>>>(sc, out_top);
    // ctx = attn @ v  -> (B,S,H*DH)
    gemm_big<<<dim3(1, 4, 48), 256>>>(sc, v, nullptr, ctx, 512, 64, 512,
                                      (long)Ssz * Ssz, (long)Ssz * DHn,
                                      (long)Ssz * Dsz, 64, Dsz,
                                      0, 1.0f, 0);
    // A = attn . structure
    acc_A<<<dim3(512, 4), 384>>>(sc, structure, Aacc);
    // ctx += A @ Wsv + bsv
    add_sv<<<6144, 256>>>(Aacc, Wsv, bsv, ctx);
    // out = ctx @ Wo + bo
    gemm_big<<<dim3(12, 16, 1), 256>>>(ctx, Wo, bo, out, 2048, 768, 768,
                                       0, 0, 0, 0, 768, 0, 1.0f, 0);
}